// round 1
// baseline (speedup 1.0000x reference)
#include <cuda_runtime.h>

// Soft VQ encoding, fused fp32:
//   D = S[k]*(||x||^2 + ||c_k||^2 - 2 x.c_k);  A = softmax_k(D);
//   E[b,k,:] = sum_n A[b,n,k]*(X[b,n,:] - C[k,:])
// Shapes: X (8,16384,128) f32, C (128,128) f32, S (128,) f32 -> E (8,128,128) f32.

#define B_   8
#define N_   16384
#define D_   128
#define K_   128
#define CH   128          // rows per chunk
#define PAD  132          // padded row length in floats (conflict-free LDS)
#define CPB  19           // CTAs per batch
#define GRID (B_ * CPB)   // 152
#define NT   256
#define CHUNKS_PER_B (N_ / CH)   // 128

#define SMEM_FLOATS (3 * K_ * PAD + 4 * K_)
#define SMEM_BYTES  (SMEM_FLOATS * 4)

// Exclusive per-CTA partial results (deterministic, no atomics). ~10 MB.
__device__ float g_partial[(size_t)GRID * K_ * D_];

__global__ __launch_bounds__(NT, 1)
void vq_fused_kernel(const float* __restrict__ X,
                     const float* __restrict__ C,
                     const float* __restrict__ S)
{
    extern __shared__ float smem[];
    float* Cs  = smem;                    // [K_][PAD]
    float* Xs  = Cs + K_ * PAD;           // [CH][PAD]
    float* As  = Xs + CH * PAD;           // [CH][PAD]  xc then A
    float* Sm2 = As + CH * PAD;           // -2*S        [K_]
    float* Ssc = Sm2 + K_;                // S*||c||^2   [K_]
    float* Ss  = Ssc + K_;                // S           [K_]
    float* COL = Ss + K_;                 // per-chunk col sums [K_]

    const int tid = threadIdx.x;
    const int kg  = tid >> 4;             // 0..15  (k group of 8)
    const int rg  = tid & 15;             // 0..15  (row group / d group)
    const int lane = tid & 31;
    const int wrp  = tid >> 5;
    const int kl   = lane * 4;            // softmax lane's 4 k columns

    // ---- load C into padded smem (coalesced) ----
    for (int i = tid; i < K_ * (D_ / 4); i += NT) {
        int k  = i >> 5;
        int d4 = i & 31;
        float4 v = reinterpret_cast<const float4*>(C)[i];
        *reinterpret_cast<float4*>(&Cs[k * PAD + d4 * 4]) = v;
    }
    __syncthreads();

    // ---- per-codeword constants ----
    if (tid < K_) {
        float c2 = 0.f;
        #pragma unroll
        for (int d4 = 0; d4 < 32; d4++) {
            float4 v = *reinterpret_cast<float4*>(&Cs[tid * PAD + d4 * 4]);
            c2 += v.x * v.x + v.y * v.y + v.z * v.z + v.w * v.w;
        }
        float s = S[tid];
        Ss[tid]  = s;
        Sm2[tid] = -2.f * s;
        Ssc[tid] = s * c2;
    }
    __syncthreads();

    // per-lane softmax constants (fixed k columns for this lane)
    float4 m2v = *reinterpret_cast<float4*>(&Sm2[kl]);
    float4 scv = *reinterpret_cast<float4*>(&Ssc[kl]);
    float4 ssv = *reinterpret_cast<float4*>(&Ss[kl]);

    // ---- chunk range for this CTA (contiguous within one batch) ----
    const int b   = blockIdx.x / CPB;
    const int t   = blockIdx.x % CPB;
    const int base = CHUNKS_PER_B / CPB;      // 6
    const int rem  = CHUNKS_PER_B % CPB;      // 14
    const int cnt  = base + (t < rem ? 1 : 0);
    const int st   = t * base + (t < rem ? t : rem);

    float* P = g_partial + (size_t)blockIdx.x * (K_ * D_);

    for (int ci = 0; ci < cnt; ci++) {
        const int chunk = st + ci;
        const float* Xg = X + ((size_t)b * N_ + (size_t)chunk * CH) * (size_t)D_;

        // ---- load X chunk ----
        for (int i = tid; i < CH * (D_ / 4); i += NT) {
            int r  = i >> 5;
            int d4 = i & 31;
            float4 v = reinterpret_cast<const float4*>(Xg)[i];
            *reinterpret_cast<float4*>(&Xs[r * PAD + d4 * 4]) = v;
        }
        __syncthreads();

        // ---- phase 1: XC = X . C^T  (8x8 register tile per thread) ----
        {
            float acc[8][8];
            #pragma unroll
            for (int i = 0; i < 8; i++)
                #pragma unroll
                for (int j = 0; j < 8; j++) acc[i][j] = 0.f;

            #pragma unroll 1
            for (int d4 = 0; d4 < 32; d4++) {
                float4 xv[8];
                #pragma unroll
                for (int i = 0; i < 8; i++)
                    xv[i] = *reinterpret_cast<const float4*>(&Xs[(rg + 16 * i) * PAD + d4 * 4]);
                #pragma unroll
                for (int j = 0; j < 8; j++) {
                    float4 cv = *reinterpret_cast<const float4*>(&Cs[(kg * 8 + j) * PAD + d4 * 4]);
                    #pragma unroll
                    for (int i = 0; i < 8; i++) {
                        acc[i][j] = fmaf(xv[i].x, cv.x, acc[i][j]);
                        acc[i][j] = fmaf(xv[i].y, cv.y, acc[i][j]);
                        acc[i][j] = fmaf(xv[i].z, cv.z, acc[i][j]);
                        acc[i][j] = fmaf(xv[i].w, cv.w, acc[i][j]);
                    }
                }
            }
            #pragma unroll
            for (int i = 0; i < 8; i++) {
                int r = rg + 16 * i;
                *reinterpret_cast<float4*>(&As[r * PAD + kg * 8]) =
                    make_float4(acc[i][0], acc[i][1], acc[i][2], acc[i][3]);
                *reinterpret_cast<float4*>(&As[r * PAD + kg * 8 + 4]) =
                    make_float4(acc[i][4], acc[i][5], acc[i][6], acc[i][7]);
            }
        }
        __syncthreads();

        // ---- phase 2: per-row softmax of D = m2*xc + (S*X2 + S*C2) ----
        #pragma unroll 1
        for (int rr = 0; rr < 16; rr++) {
            int r = wrp * 16 + rr;
            float4 xv = *reinterpret_cast<float4*>(&Xs[r * PAD + kl]);
            float x2 = xv.x * xv.x + xv.y * xv.y + xv.z * xv.z + xv.w * xv.w;
            #pragma unroll
            for (int o = 16; o > 0; o >>= 1) x2 += __shfl_xor_sync(0xffffffffu, x2, o);

            float4 xc = *reinterpret_cast<float4*>(&As[r * PAD + kl]);
            float d0 = fmaf(m2v.x, xc.x, fmaf(ssv.x, x2, scv.x));
            float d1 = fmaf(m2v.y, xc.y, fmaf(ssv.y, x2, scv.y));
            float d2 = fmaf(m2v.z, xc.z, fmaf(ssv.z, x2, scv.z));
            float d3 = fmaf(m2v.w, xc.w, fmaf(ssv.w, x2, scv.w));

            float mx = fmaxf(fmaxf(d0, d1), fmaxf(d2, d3));
            #pragma unroll
            for (int o = 16; o > 0; o >>= 1) mx = fmaxf(mx, __shfl_xor_sync(0xffffffffu, mx, o));

            float e0 = __expf(d0 - mx);
            float e1 = __expf(d1 - mx);
            float e2 = __expf(d2 - mx);
            float e3 = __expf(d3 - mx);
            float sm = e0 + e1 + e2 + e3;
            #pragma unroll
            for (int o = 16; o > 0; o >>= 1) sm += __shfl_xor_sync(0xffffffffu, sm, o);
            float inv = 1.f / sm;
            *reinterpret_cast<float4*>(&As[r * PAD + kl]) =
                make_float4(e0 * inv, e1 * inv, e2 * inv, e3 * inv);
        }
        __syncthreads();

        // ---- phase 3: E += A^T . X  (8k x 8d register tile per thread) ----
        {
            float eacc[8][8];
            float cacc[8];
            #pragma unroll
            for (int i = 0; i < 8; i++) {
                cacc[i] = 0.f;
                #pragma unroll
                for (int j = 0; j < 8; j++) eacc[i][j] = 0.f;
            }

            #pragma unroll 1
            for (int n = 0; n < CH; n++) {
                float4 a0 = *reinterpret_cast<float4*>(&As[n * PAD + kg * 8]);
                float4 a1 = *reinterpret_cast<float4*>(&As[n * PAD + kg * 8 + 4]);
                float4 x0 = *reinterpret_cast<float4*>(&Xs[n * PAD + rg * 8]);
                float4 x1 = *reinterpret_cast<float4*>(&Xs[n * PAD + rg * 8 + 4]);
                float av[8] = {a0.x, a0.y, a0.z, a0.w, a1.x, a1.y, a1.z, a1.w};
                float xw[8] = {x0.x, x0.y, x0.z, x0.w, x1.x, x1.y, x1.z, x1.w};
                #pragma unroll
                for (int kk = 0; kk < 8; kk++)
                    #pragma unroll
                    for (int dd = 0; dd < 8; dd++)
                        eacc[kk][dd] = fmaf(av[kk], xw[dd], eacc[kk][dd]);
                if (rg == 0) {
                    #pragma unroll
                    for (int kk = 0; kk < 8; kk++) cacc[kk] += av[kk];
                }
            }

            if (rg == 0) {
                #pragma unroll
                for (int kk = 0; kk < 8; kk++) COL[kg * 8 + kk] = cacc[kk];
            }
            __syncthreads();

            // flush this chunk's contribution into the CTA's exclusive partial
            const bool first = (ci == 0);
            #pragma unroll
            for (int kk = 0; kk < 8; kk++) {
                int k = kg * 8 + kk;
                float cs = COL[k];
                #pragma unroll
                for (int q = 0; q < 2; q++) {
                    int d = rg * 8 + q * 4;
                    float4 cv = *reinterpret_cast<float4*>(&Cs[k * PAD + d]);
                    float4 add;
                    add.x = eacc[kk][q * 4 + 0] - cs * cv.x;
                    add.y = eacc[kk][q * 4 + 1] - cs * cv.y;
                    add.z = eacc[kk][q * 4 + 2] - cs * cv.z;
                    add.w = eacc[kk][q * 4 + 3] - cs * cv.w;
                    float4* pp = reinterpret_cast<float4*>(&P[k * D_ + d]);
                    if (first) {
                        *pp = add;
                    } else {
                        float4 old = *pp;
                        old.x += add.x; old.y += add.y; old.z += add.z; old.w += add.w;
                        *pp = old;
                    }
                }
            }
        }
        __syncthreads();   // protect Xs/As/COL before next chunk
    }
}

__global__ void vq_reduce_kernel(float* __restrict__ out)
{
    int i = blockIdx.x * blockDim.x + threadIdx.x;
    if (i >= B_ * K_ * D_) return;
    int b = i >> 14;                  // / (K_*D_)
    int j = i & (K_ * D_ - 1);
    float s = 0.f;
    #pragma unroll
    for (int t = 0; t < CPB; t++)
        s += g_partial[((size_t)(b * CPB + t)) * (K_ * D_) + j];
    out[i] = s;
}

extern "C" void kernel_launch(void* const* d_in, const int* in_sizes, int n_in,
                              void* d_out, int out_size)
{
    const float* X = nullptr;
    const float* C = nullptr;
    const float* S = nullptr;
    for (int i = 0; i < n_in; i++) {
        if (in_sizes[i] == B_ * N_ * D_)      X = (const float*)d_in[i];
        else if (in_sizes[i] == K_ * D_)      C = (const float*)d_in[i];
        else if (in_sizes[i] == K_)           S = (const float*)d_in[i];
    }
    float* out = (float*)d_out;

    cudaFuncSetAttribute(vq_fused_kernel,
                         cudaFuncAttributeMaxDynamicSharedMemorySize, SMEM_BYTES);
    vq_fused_kernel<<<GRID, NT, SMEM_BYTES>>>(X, C, S);
    vq_reduce_kernel<<<(B_ * K_ * D_ + 255) / 256, 256>>>(out);
}

// round 3
// speedup vs baseline: 1.1050x; 1.1050x over previous
#include <cuda_runtime.h>

// Soft VQ encoding, fused fp32, packed-f32x2 (FFMA2) GEMM phases.
//   D = S[k]*(||x||^2 + ||c_k||^2 - 2 x.c_k);  A = softmax_k(D);
//   E[b,k,:] = sum_n A[b,n,k]*(X[b,n,:] - C[k,:])
// Shapes: X (8,16384,128) f32, C (128,128) f32, S (128,) f32 -> E (8,128,128) f32.

#define B_   8
#define N_   16384
#define D_   128
#define K_   128
#define CH   128          // rows per chunk
#define PAD  132          // padded row length in floats (132*4=528 B, 16B-aligned rows)
#define CPB  19           // CTAs per batch
#define GRID (B_ * CPB)   // 152
#define NT   256
#define CHUNKS_PER_B (N_ / CH)   // 128

#define SMEM_FLOATS (3 * K_ * PAD + 4 * K_)
#define SMEM_BYTES  (SMEM_FLOATS * 4)

typedef unsigned long long u64;

// packed f32x2 FMA: d = a*b + c elementwise on two packed floats
__device__ __forceinline__ u64 ffma2(u64 a, u64 b, u64 c) {
    u64 d;
    asm("fma.rn.f32x2 %0, %1, %2, %3;" : "=l"(d) : "l"(a), "l"(b), "l"(c));
    return d;
}
__device__ __forceinline__ u64 pk2(float lo, float hi) {
    u64 d;
    asm("mov.b64 %0, {%1, %2};" : "=l"(d) : "f"(lo), "f"(hi));
    return d;
}
__device__ __forceinline__ void upk2(float& lo, float& hi, u64 v) {
    asm("mov.b64 {%0, %1}, %2;" : "=f"(lo), "=f"(hi) : "l"(v));
}

// Exclusive per-CTA partial results (deterministic, no atomics). ~10 MB.
__device__ float g_partial[(size_t)GRID * K_ * D_];

__global__ __launch_bounds__(NT, 1)
void vq_fused_kernel(const float* __restrict__ X,
                     const float* __restrict__ C,
                     const float* __restrict__ S)
{
    extern __shared__ float smem[];
    float* Cs  = smem;                    // [K_][PAD]
    float* Xs  = Cs + K_ * PAD;           // [CH][PAD]
    float* As  = Xs + CH * PAD;           // [CH][PAD]  xc then A
    float* Sm2 = As + CH * PAD;           // -2*S        [K_]
    float* Ssc = Sm2 + K_;                // S*||c||^2   [K_]
    float* Ss  = Ssc + K_;                // S           [K_]
    float* COL = Ss + K_;                 // colsum      [K_]

    const int tid = threadIdx.x;
    const int kg  = tid >> 4;             // 0..15  (k group of 8)
    const int rg  = tid & 15;             // 0..15  (row group / d group)
    const int lane = tid & 31;
    const int wrp  = tid >> 5;
    const int kl   = lane * 4;            // softmax lane's 4 k columns

    // ---- load C into padded smem (coalesced) ----
    for (int i = tid; i < K_ * (D_ / 4); i += NT) {
        int k  = i >> 5;
        int d4 = i & 31;
        float4 v = reinterpret_cast<const float4*>(C)[i];
        *reinterpret_cast<float4*>(&Cs[k * PAD + d4 * 4]) = v;
    }
    __syncthreads();

    // ---- per-codeword constants ----
    if (tid < K_) {
        float c2 = 0.f;
        #pragma unroll
        for (int d4 = 0; d4 < 32; d4++) {
            float4 v = *reinterpret_cast<float4*>(&Cs[tid * PAD + d4 * 4]);
            c2 += v.x * v.x + v.y * v.y + v.z * v.z + v.w * v.w;
        }
        float s = S[tid];
        Ss[tid]  = s;
        Sm2[tid] = -2.f * s;
        Ssc[tid] = s * c2;
    }
    __syncthreads();

    // per-lane softmax constants
    float4 m2v = *reinterpret_cast<float4*>(&Sm2[kl]);
    float4 scv = *reinterpret_cast<float4*>(&Ssc[kl]);
    float4 ssv = *reinterpret_cast<float4*>(&Ss[kl]);

    // ---- chunk range for this CTA ----
    const int b   = blockIdx.x / CPB;
    const int t   = blockIdx.x % CPB;
    const int base = CHUNKS_PER_B / CPB;      // 6
    const int rem  = CHUNKS_PER_B % CPB;      // 14
    const int cnt  = base + (t < rem ? 1 : 0);
    const int st   = t * base + (t < rem ? t : rem);

    // persistent output accumulators (packed d-pairs) + colsum, live across chunks
    u64 eacc2[8][4];
    float cacc[8];
    #pragma unroll
    for (int i = 0; i < 8; i++) {
        cacc[i] = 0.f;
        #pragma unroll
        for (int j = 0; j < 4; j++) eacc2[i][j] = 0ull;
    }

    for (int ci = 0; ci < cnt; ci++) {
        const int chunk = st + ci;
        const float* Xg = X + ((size_t)b * N_ + (size_t)chunk * CH) * (size_t)D_;

        // ---- load X chunk ----
        for (int i = tid; i < CH * (D_ / 4); i += NT) {
            int r  = i >> 5;
            int d4 = i & 31;
            float4 v = reinterpret_cast<const float4*>(Xg)[i];
            *reinterpret_cast<float4*>(&Xs[r * PAD + d4 * 4]) = v;
        }
        __syncthreads();

        // ---- phase 1: XC = X . C^T  (8 rows x 8 k per thread, two j-halves,
        //      f32x2 packed along d; even/odd-d partial sums folded at end) ----
        #pragma unroll
        for (int jh = 0; jh < 2; jh++) {
            u64 acc2[8][4];
            #pragma unroll
            for (int i = 0; i < 8; i++)
                #pragma unroll
                for (int j = 0; j < 4; j++) acc2[i][j] = 0ull;

            #pragma unroll 1
            for (int d4 = 0; d4 < 32; d4++) {
                ulonglong2 xv[8];
                #pragma unroll
                for (int i = 0; i < 8; i++)
                    xv[i] = *reinterpret_cast<const ulonglong2*>(
                        &Xs[(rg + 16 * i) * PAD + d4 * 4]);
                #pragma unroll
                for (int j = 0; j < 4; j++) {
                    ulonglong2 cv = *reinterpret_cast<const ulonglong2*>(
                        &Cs[(kg * 8 + jh * 4 + j) * PAD + d4 * 4]);
                    #pragma unroll
                    for (int i = 0; i < 8; i++) {
                        acc2[i][j] = ffma2(xv[i].x, cv.x, acc2[i][j]);
                        acc2[i][j] = ffma2(xv[i].y, cv.y, acc2[i][j]);
                    }
                }
            }
            // fold packed partials and store 4 consecutive k as float4
            #pragma unroll
            for (int i = 0; i < 8; i++) {
                float r0l, r0h, r1l, r1h, r2l, r2h, r3l, r3h;
                upk2(r0l, r0h, acc2[i][0]);
                upk2(r1l, r1h, acc2[i][1]);
                upk2(r2l, r2h, acc2[i][2]);
                upk2(r3l, r3h, acc2[i][3]);
                *reinterpret_cast<float4*>(&As[(rg + 16 * i) * PAD + kg * 8 + jh * 4]) =
                    make_float4(r0l + r0h, r1l + r1h, r2l + r2h, r3l + r3h);
            }
        }
        __syncthreads();

        // ---- phase 2: per-row softmax of D = m2*xc + (S*X2 + S*C2) ----
        #pragma unroll 1
        for (int rr = 0; rr < 16; rr++) {
            int r = wrp * 16 + rr;
            float4 xv = *reinterpret_cast<float4*>(&Xs[r * PAD + kl]);
            float x2 = xv.x * xv.x + xv.y * xv.y + xv.z * xv.z + xv.w * xv.w;
            #pragma unroll
            for (int o = 16; o > 0; o >>= 1) x2 += __shfl_xor_sync(0xffffffffu, x2, o);

            float4 xc = *reinterpret_cast<float4*>(&As[r * PAD + kl]);
            float d0 = fmaf(m2v.x, xc.x, fmaf(ssv.x, x2, scv.x));
            float d1 = fmaf(m2v.y, xc.y, fmaf(ssv.y, x2, scv.y));
            float d2 = fmaf(m2v.z, xc.z, fmaf(ssv.z, x2, scv.z));
            float d3 = fmaf(m2v.w, xc.w, fmaf(ssv.w, x2, scv.w));

            float mx = fmaxf(fmaxf(d0, d1), fmaxf(d2, d3));
            #pragma unroll
            for (int o = 16; o > 0; o >>= 1) mx = fmaxf(mx, __shfl_xor_sync(0xffffffffu, mx, o));

            float e0 = __expf(d0 - mx);
            float e1 = __expf(d1 - mx);
            float e2 = __expf(d2 - mx);
            float e3 = __expf(d3 - mx);
            float sm = e0 + e1 + e2 + e3;
            #pragma unroll
            for (int o = 16; o > 0; o >>= 1) sm += __shfl_xor_sync(0xffffffffu, sm, o);
            float inv = 1.f / sm;
            *reinterpret_cast<float4*>(&As[r * PAD + kl]) =
                make_float4(e0 * inv, e1 * inv, e2 * inv, e3 * inv);
        }
        __syncthreads();

        // ---- phase 3: E += A^T . X  (8 k x 8 d per thread, f32x2 packed along d;
        //      accumulators persist across chunks in registers) ----
        #pragma unroll 1
        for (int n = 0; n < CH; n++) {
            float4 a0 = *reinterpret_cast<float4*>(&As[n * PAD + kg * 8]);
            float4 a1 = *reinterpret_cast<float4*>(&As[n * PAD + kg * 8 + 4]);
            ulonglong2 x0 = *reinterpret_cast<ulonglong2*>(&Xs[n * PAD + rg * 8]);
            ulonglong2 x1 = *reinterpret_cast<ulonglong2*>(&Xs[n * PAD + rg * 8 + 4]);
            u64 xp[4] = {x0.x, x0.y, x1.x, x1.y};
            float av[8] = {a0.x, a0.y, a0.z, a0.w, a1.x, a1.y, a1.z, a1.w};
            #pragma unroll
            for (int kk = 0; kk < 8; kk++) {
                u64 ap = pk2(av[kk], av[kk]);
                #pragma unroll
                for (int p = 0; p < 4; p++)
                    eacc2[kk][p] = ffma2(ap, xp[p], eacc2[kk][p]);
            }
            if (rg == 0) {
                #pragma unroll
                for (int kk = 0; kk < 8; kk++) cacc[kk] += av[kk];
            }
        }
        __syncthreads();   // As/Xs reused next chunk
    }

    // ---- final flush: P = E_partial - colsum * C ----
    if (rg == 0) {
        #pragma unroll
        for (int kk = 0; kk < 8; kk++) COL[kg * 8 + kk] = cacc[kk];
    }
    __syncthreads();

    float* P = g_partial + (size_t)blockIdx.x * (K_ * D_);
    #pragma unroll
    for (int kk = 0; kk < 8; kk++) {
        int k = kg * 8 + kk;
        float cs = COL[k];
        float e[8];
        #pragma unroll
        for (int p = 0; p < 4; p++) upk2(e[2 * p], e[2 * p + 1], eacc2[kk][p]);
        #pragma unroll
        for (int q = 0; q < 2; q++) {
            int d = rg * 8 + q * 4;
            float4 cv = *reinterpret_cast<float4*>(&Cs[k * PAD + d]);
            float4 o;
            o.x = e[q * 4 + 0] - cs * cv.x;
            o.y = e[q * 4 + 1] - cs * cv.y;
            o.z = e[q * 4 + 2] - cs * cv.z;
            o.w = e[q * 4 + 3] - cs * cv.w;
            *reinterpret_cast<float4*>(&P[k * D_ + d]) = o;
        }
    }
}

__global__ void vq_reduce_kernel(float* __restrict__ out)
{
    int i = blockIdx.x * blockDim.x + threadIdx.x;   // float4 index
    if (i >= (B_ * K_ * D_) / 4) return;
    int b = i >> 12;                  // / (K_*D_/4)
    int j = i & (K_ * D_ / 4 - 1);
    float4 s = make_float4(0.f, 0.f, 0.f, 0.f);
    #pragma unroll
    for (int t = 0; t < CPB; t++) {
        float4 v = reinterpret_cast<const float4*>(
            g_partial + ((size_t)(b * CPB + t)) * (K_ * D_))[j];
        s.x += v.x; s.y += v.y; s.z += v.z; s.w += v.w;
    }
    reinterpret_cast<float4*>(out)[i] = s;
}

extern "C" void kernel_launch(void* const* d_in, const int* in_sizes, int n_in,
                              void* d_out, int out_size)
{
    const float* X = nullptr;
    const float* C = nullptr;
    const float* S = nullptr;
    for (int i = 0; i < n_in; i++) {
        if (in_sizes[i] == B_ * N_ * D_)      X = (const float*)d_in[i];
        else if (in_sizes[i] == K_ * D_)      C = (const float*)d_in[i];
        else if (in_sizes[i] == K_)           S = (const float*)d_in[i];
    }
    float* out = (float*)d_out;

    cudaFuncSetAttribute(vq_fused_kernel,
                         cudaFuncAttributeMaxDynamicSharedMemorySize, SMEM_BYTES);
    vq_fused_kernel<<<GRID, NT, SMEM_BYTES>>>(X, C, S);
    vq_reduce_kernel<<<(B_ * K_ * D_ / 4 + 255) / 256, 256>>>(out);
}

// round 4
// speedup vs baseline: 1.1666x; 1.0558x over previous
#include <cuda_runtime.h>

// Soft VQ encoding, fused fp32, packed-f32x2 (FFMA2) GEMM phases.
//   D = S[k]*(||x||^2 + ||c_k||^2 - 2 x.c_k);  A = softmax_k(D);
//   E[b,k,:] = sum_n A[b,n,k]*(X[b,n,:] - C[k,:])
// Shapes: X (8,16384,128) f32, C (128,128) f32, S (128,) f32 -> E (8,128,128) f32.

#define B_   8
#define N_   16384
#define D_   128
#define K_   128
#define CH   128          // rows per chunk
#define PAD  132          // padded row length in floats (132*4=528 B, 16B-aligned rows)
#define CPB  19           // CTAs per batch
#define GRID (B_ * CPB)   // 152
#define NT   256
#define CHUNKS_PER_B (N_ / CH)   // 128

#define SMEM_FLOATS (3 * K_ * PAD + 4 * K_)
#define SMEM_BYTES  (SMEM_FLOATS * 4)

typedef unsigned long long u64;

// packed f32x2 FMA: d = a*b + c elementwise on two packed floats
__device__ __forceinline__ u64 ffma2(u64 a, u64 b, u64 c) {
    u64 d;
    asm("fma.rn.f32x2 %0, %1, %2, %3;" : "=l"(d) : "l"(a), "l"(b), "l"(c));
    return d;
}
__device__ __forceinline__ u64 pk2(float lo, float hi) {
    u64 d;
    asm("mov.b64 %0, {%1, %2};" : "=l"(d) : "f"(lo), "f"(hi));
    return d;
}
__device__ __forceinline__ void upk2(float& lo, float& hi, u64 v) {
    asm("mov.b64 {%0, %1}, %2;" : "=f"(lo), "=f"(hi) : "l"(v));
}

// Exclusive per-CTA partial results (deterministic, no atomics). ~10 MB.
__device__ float g_partial[(size_t)GRID * K_ * D_];

__global__ __launch_bounds__(NT, 1)
void vq_fused_kernel(const float* __restrict__ X,
                     const float* __restrict__ C,
                     const float* __restrict__ S)
{
    extern __shared__ float smem[];
    float* Cs  = smem;                    // [K_][PAD]
    float* Xs  = Cs + K_ * PAD;           // [CH][PAD]
    float* As  = Xs + CH * PAD;           // [CH][PAD]  xc then A
    float* Sm2 = As + CH * PAD;           // -2*S        [K_]
    float* Ssc = Sm2 + K_;                // S*||c||^2   [K_]
    float* Ss  = Ssc + K_;                // S           [K_]
    float* COL = Ss + K_;                 // colsum      [K_]

    const int tid = threadIdx.x;
    const int kg  = tid >> 4;             // 0..15  (k group of 8)
    const int rg  = tid & 15;             // 0..15  (row group / d group)
    const int lane = tid & 31;
    const int wrp  = tid >> 5;
    const int kl   = lane * 4;            // softmax lane's 4 k columns

    // ---- load C into padded smem (coalesced) ----
    for (int i = tid; i < K_ * (D_ / 4); i += NT) {
        int k  = i >> 5;
        int d4 = i & 31;
        float4 v = reinterpret_cast<const float4*>(C)[i];
        *reinterpret_cast<float4*>(&Cs[k * PAD + d4 * 4]) = v;
    }
    __syncthreads();

    // ---- per-codeword constants ----
    if (tid < K_) {
        float c2 = 0.f;
        #pragma unroll
        for (int d4 = 0; d4 < 32; d4++) {
            float4 v = *reinterpret_cast<float4*>(&Cs[tid * PAD + d4 * 4]);
            c2 += v.x * v.x + v.y * v.y + v.z * v.z + v.w * v.w;
        }
        float s = S[tid];
        Ss[tid]  = s;
        Sm2[tid] = -2.f * s;
        Ssc[tid] = s * c2;
    }
    __syncthreads();

    // per-lane softmax constants
    float4 m2v = *reinterpret_cast<float4*>(&Sm2[kl]);
    float4 scv = *reinterpret_cast<float4*>(&Ssc[kl]);
    float4 ssv = *reinterpret_cast<float4*>(&Ss[kl]);

    // ---- chunk range for this CTA ----
    const int b   = blockIdx.x / CPB;
    const int t   = blockIdx.x % CPB;
    const int base = CHUNKS_PER_B / CPB;      // 6
    const int rem  = CHUNKS_PER_B % CPB;      // 14
    const int cnt  = base + (t < rem ? 1 : 0);
    const int st   = t * base + (t < rem ? t : rem);

    // persistent output accumulators (packed d-pairs) + colsum, live across chunks
    u64 eacc2[8][4];
    float cacc[8];
    #pragma unroll
    for (int i = 0; i < 8; i++) {
        cacc[i] = 0.f;
        #pragma unroll
        for (int j = 0; j < 4; j++) eacc2[i][j] = 0ull;
    }

    for (int ci = 0; ci < cnt; ci++) {
        const int chunk = st + ci;
        const float* Xg = X + ((size_t)b * N_ + (size_t)chunk * CH) * (size_t)D_;

        // ---- load X chunk ----
        for (int i = tid; i < CH * (D_ / 4); i += NT) {
            int r  = i >> 5;
            int d4 = i & 31;
            float4 v = reinterpret_cast<const float4*>(Xg)[i];
            *reinterpret_cast<float4*>(&Xs[r * PAD + d4 * 4]) = v;
        }
        __syncthreads();

        // ---- phase 1: XC = X . C^T  (8 rows x 8 k per thread, two j-halves,
        //      f32x2 packed along d; even/odd-d partial sums folded at end) ----
        #pragma unroll
        for (int jh = 0; jh < 2; jh++) {
            u64 acc2[8][4];
            #pragma unroll
            for (int i = 0; i < 8; i++)
                #pragma unroll
                for (int j = 0; j < 4; j++) acc2[i][j] = 0ull;

            #pragma unroll 1
            for (int d4 = 0; d4 < 32; d4++) {
                ulonglong2 xv[8];
                #pragma unroll
                for (int i = 0; i < 8; i++)
                    xv[i] = *reinterpret_cast<const ulonglong2*>(
                        &Xs[(rg + 16 * i) * PAD + d4 * 4]);
                #pragma unroll
                for (int j = 0; j < 4; j++) {
                    ulonglong2 cv = *reinterpret_cast<const ulonglong2*>(
                        &Cs[(kg * 8 + jh * 4 + j) * PAD + d4 * 4]);
                    #pragma unroll
                    for (int i = 0; i < 8; i++) {
                        acc2[i][j] = ffma2(xv[i].x, cv.x, acc2[i][j]);
                        acc2[i][j] = ffma2(xv[i].y, cv.y, acc2[i][j]);
                    }
                }
            }
            // fold packed partials and store 4 consecutive k as float4
            #pragma unroll
            for (int i = 0; i < 8; i++) {
                float r0l, r0h, r1l, r1h, r2l, r2h, r3l, r3h;
                upk2(r0l, r0h, acc2[i][0]);
                upk2(r1l, r1h, acc2[i][1]);
                upk2(r2l, r2h, acc2[i][2]);
                upk2(r3l, r3h, acc2[i][3]);
                *reinterpret_cast<float4*>(&As[(rg + 16 * i) * PAD + kg * 8 + jh * 4]) =
                    make_float4(r0l + r0h, r1l + r1h, r2l + r2h, r3l + r3h);
            }
        }
        __syncthreads();

        // ---- phase 2: per-row softmax of D = m2*xc + (S*X2 + S*C2) ----
        #pragma unroll 1
        for (int rr = 0; rr < 16; rr++) {
            int r = wrp * 16 + rr;
            float4 xv = *reinterpret_cast<float4*>(&Xs[r * PAD + kl]);
            float x2 = xv.x * xv.x + xv.y * xv.y + xv.z * xv.z + xv.w * xv.w;
            #pragma unroll
            for (int o = 16; o > 0; o >>= 1) x2 += __shfl_xor_sync(0xffffffffu, x2, o);

            float4 xc = *reinterpret_cast<float4*>(&As[r * PAD + kl]);
            float d0 = fmaf(m2v.x, xc.x, fmaf(ssv.x, x2, scv.x));
            float d1 = fmaf(m2v.y, xc.y, fmaf(ssv.y, x2, scv.y));
            float d2 = fmaf(m2v.z, xc.z, fmaf(ssv.z, x2, scv.z));
            float d3 = fmaf(m2v.w, xc.w, fmaf(ssv.w, x2, scv.w));

            float mx = fmaxf(fmaxf(d0, d1), fmaxf(d2, d3));
            #pragma unroll
            for (int o = 16; o > 0; o >>= 1) mx = fmaxf(mx, __shfl_xor_sync(0xffffffffu, mx, o));

            float e0 = __expf(d0 - mx);
            float e1 = __expf(d1 - mx);
            float e2 = __expf(d2 - mx);
            float e3 = __expf(d3 - mx);
            float sm = e0 + e1 + e2 + e3;
            #pragma unroll
            for (int o = 16; o > 0; o >>= 1) sm += __shfl_xor_sync(0xffffffffu, sm, o);
            float inv = 1.f / sm;
            *reinterpret_cast<float4*>(&As[r * PAD + kl]) =
                make_float4(e0 * inv, e1 * inv, e2 * inv, e3 * inv);
        }
        __syncthreads();

        // ---- phase 3: E += A^T . X  (8 k x 8 d per thread, f32x2 packed along d;
        //      accumulators persist across chunks in registers) ----
        #pragma unroll 1
        for (int n = 0; n < CH; n++) {
            float4 a0 = *reinterpret_cast<float4*>(&As[n * PAD + kg * 8]);
            float4 a1 = *reinterpret_cast<float4*>(&As[n * PAD + kg * 8 + 4]);
            ulonglong2 x0 = *reinterpret_cast<ulonglong2*>(&Xs[n * PAD + rg * 8]);
            ulonglong2 x1 = *reinterpret_cast<ulonglong2*>(&Xs[n * PAD + rg * 8 + 4]);
            u64 xp[4] = {x0.x, x0.y, x1.x, x1.y};
            float av[8] = {a0.x, a0.y, a0.z, a0.w, a1.x, a1.y, a1.z, a1.w};
            #pragma unroll
            for (int kk = 0; kk < 8; kk++) {
                u64 ap = pk2(av[kk], av[kk]);
                #pragma unroll
                for (int p = 0; p < 4; p++)
                    eacc2[kk][p] = ffma2(ap, xp[p], eacc2[kk][p]);
            }
            if (rg == 0) {
                #pragma unroll
                for (int kk = 0; kk < 8; kk++) cacc[kk] += av[kk];
            }
        }
        __syncthreads();   // As/Xs reused next chunk
    }

    // ---- final flush: P = E_partial - colsum * C ----
    if (rg == 0) {
        #pragma unroll
        for (int kk = 0; kk < 8; kk++) COL[kg * 8 + kk] = cacc[kk];
    }
    __syncthreads();

    float* P = g_partial + (size_t)blockIdx.x * (K_ * D_);
    #pragma unroll
    for (int kk = 0; kk < 8; kk++) {
        int k = kg * 8 + kk;
        float cs = COL[k];
        float e[8];
        #pragma unroll
        for (int p = 0; p < 4; p++) upk2(e[2 * p], e[2 * p + 1], eacc2[kk][p]);
        #pragma unroll
        for (int q = 0; q < 2; q++) {
            int d = rg * 8 + q * 4;
            float4 cv = *reinterpret_cast<float4*>(&Cs[k * PAD + d]);
            float4 o;
            o.x = e[q * 4 + 0] - cs * cv.x;
            o.y = e[q * 4 + 1] - cs * cv.y;
            o.z = e[q * 4 + 2] - cs * cv.z;
            o.w = e[q * 4 + 3] - cs * cv.w;
            *reinterpret_cast<float4*>(&P[k * D_ + d]) = o;
        }
    }
}

__global__ void vq_reduce_kernel(float* __restrict__ out)
{
    int i = blockIdx.x * blockDim.x + threadIdx.x;   // float4 index
    if (i >= (B_ * K_ * D_) / 4) return;
    int b = i >> 12;                  // / (K_*D_/4)
    int j = i & (K_ * D_ / 4 - 1);
    float4 s = make_float4(0.f, 0.f, 0.f, 0.f);
    #pragma unroll
    for (int t = 0; t < CPB; t++) {
        float4 v = reinterpret_cast<const float4*>(
            g_partial + ((size_t)(b * CPB + t)) * (K_ * D_))[j];
        s.x += v.x; s.y += v.y; s.z += v.z; s.w += v.w;
    }
    reinterpret_cast<float4*>(out)[i] = s;
}

extern "C" void kernel_launch(void* const* d_in, const int* in_sizes, int n_in,
                              void* d_out, int out_size)
{
    const float* X = nullptr;
    const float* C = nullptr;
    const float* S = nullptr;
    for (int i = 0; i < n_in; i++) {
        if (in_sizes[i] == B_ * N_ * D_)      X = (const float*)d_in[i];
        else if (in_sizes[i] == K_ * D_)      C = (const float*)d_in[i];
        else if (in_sizes[i] == K_)           S = (const float*)d_in[i];
    }
    float* out = (float*)d_out;

    cudaFuncSetAttribute(vq_fused_kernel,
                         cudaFuncAttributeMaxDynamicSharedMemorySize, SMEM_BYTES);
    vq_fused_kernel<<<GRID, NT, SMEM_BYTES>>>(X, C, S);
    vq_reduce_kernel<<<(B_ * K_ * D_ / 4 + 255) / 256, 256>>>(out);
}